// round 1
// baseline (speedup 1.0000x reference)
#include <cuda_runtime.h>

#define INSIZE 512
#define NREFL  64
#define BATCH  8192
#define ROWS_PER_BLOCK 16   // one warp per batch row, 512 threads/block

__device__ __align__(16) float g_sigma[INSIZE];
__device__ float g_beta_u[NREFL];
__device__ float g_beta_v[NREFL];

// ---------------------------------------------------------------------------
// Prep: sigma from p, beta = 2/(u.u) for the 64 U rows and 64 V rows.
// One block, 1024 threads (32 warps); each warp does 4 norms.
// ---------------------------------------------------------------------------
__global__ void prep_kernel(const float* __restrict__ p,
                            const float* __restrict__ U,
                            const float* __restrict__ V)
{
    const int t = threadIdx.x;
    if (t < INSIZE) {
        float s = 1.0f / (1.0f + expf(-p[t]));
        g_sigma[t] = 0.1f + 0.9f * s;     // 2r*(sigmoid-0.5)+mean, r=0.45, mean=0.55
    }
    const int w = t >> 5, lane = t & 31;
    #pragma unroll
    for (int q = 0; q < 4; ++q) {
        const int n = w + 32 * q;                      // 0..127
        const float* mat = (n < NREFL) ? U : V;
        const int row = (n < NREFL) ? n : n - NREFL;
        float ss = 0.f;
        #pragma unroll
        for (int j = lane; j < INSIZE; j += 32) {
            float v = (j >= row) ? mat[row * INSIZE + j] : 0.f;  // triu mask (input is triu already; safety)
            ss += v * v;
        }
        #pragma unroll
        for (int o = 16; o > 0; o >>= 1) ss += __shfl_xor_sync(0xffffffffu, ss, o);
        if (lane == 0) {
            float b = 2.0f / ss;
            if (n < NREFL) g_beta_u[row] = b; else g_beta_v[row] = b;
        }
    }
}

// ---------------------------------------------------------------------------
// Main: each warp owns one batch row (512 floats = 4 x float4 per lane,
// element j = 16*k4' mapping j = k*128 + lane*4 + c via float4 index k*32+lane).
// Reflectors double-buffered in smem; one __syncthreads per reflection.
// ---------------------------------------------------------------------------
__global__ __launch_bounds__(512, 2)
void spectral_main(const float4* __restrict__ x,
                   const float*  __restrict__ U,
                   const float*  __restrict__ V,
                   const float4* __restrict__ bias,
                   float4* __restrict__ out)
{
    __shared__ float us[2][INSIZE];
    const int t    = threadIdx.x;
    const int w    = t >> 5;
    const int lane = t & 31;
    const int r    = blockIdx.x * ROWS_PER_BLOCK + w;

    const float4* xrow = x + (size_t)r * (INSIZE / 4);
    float4 m[4];
    #pragma unroll
    for (int k = 0; k < 4; ++k) m[k] = xrow[k * 32 + lane];

    // ---- U chain: i = 0 .. 63 ----
    us[0][t] = U[t];                       // row 0, mask trivial
    __syncthreads();

    #pragma unroll 1
    for (int i = 0; i < NREFL; ++i) {
        const int cb = i & 1, nb = cb ^ 1;
        if (i + 1 < NREFL) {
            const int ii = i + 1;
            us[nb][t] = (t >= ii) ? U[ii * INSIZE + t] : 0.f;
        }
        const float4* u4 = (const float4*)us[cb];
        float4 u[4];
        float loc = 0.f;
        #pragma unroll
        for (int k = 0; k < 4; ++k) {
            u[k] = u4[k * 32 + lane];
            loc += m[k].x * u[k].x + m[k].y * u[k].y
                 + m[k].z * u[k].z + m[k].w * u[k].w;
        }
        #pragma unroll
        for (int o = 16; o > 0; o >>= 1) loc += __shfl_xor_sync(0xffffffffu, loc, o);
        const float s = g_beta_u[i] * loc;
        #pragma unroll
        for (int k = 0; k < 4; ++k) {
            m[k].x -= s * u[k].x; m[k].y -= s * u[k].y;
            m[k].z -= s * u[k].z; m[k].w -= s * u[k].w;
        }
        __syncthreads();
    }

    // ---- Sigma scaling ----
    {
        const float4* sg = (const float4*)g_sigma;
        #pragma unroll
        for (int k = 0; k < 4; ++k) {
            float4 sv = sg[k * 32 + lane];
            m[k].x *= sv.x; m[k].y *= sv.y; m[k].z *= sv.z; m[k].w *= sv.w;
        }
    }

    // ---- V chain: i = 63 .. 0 ----
    us[0][t] = (t >= (NREFL - 1)) ? V[(NREFL - 1) * INSIZE + t] : 0.f;
    __syncthreads();

    #pragma unroll 1
    for (int ii = 0; ii < NREFL; ++ii) {
        const int i  = NREFL - 1 - ii;
        const int cb = ii & 1, nb = cb ^ 1;
        if (i > 0) {
            const int inx = i - 1;
            us[nb][t] = (t >= inx) ? V[inx * INSIZE + t] : 0.f;
        }
        const float4* v4 = (const float4*)us[cb];
        float4 u[4];
        float loc = 0.f;
        #pragma unroll
        for (int k = 0; k < 4; ++k) {
            u[k] = v4[k * 32 + lane];
            loc += m[k].x * u[k].x + m[k].y * u[k].y
                 + m[k].z * u[k].z + m[k].w * u[k].w;
        }
        #pragma unroll
        for (int o = 16; o > 0; o >>= 1) loc += __shfl_xor_sync(0xffffffffu, loc, o);
        const float s = g_beta_v[i] * loc;
        #pragma unroll
        for (int k = 0; k < 4; ++k) {
            m[k].x -= s * u[k].x; m[k].y -= s * u[k].y;
            m[k].z -= s * u[k].z; m[k].w -= s * u[k].w;
        }
        __syncthreads();
    }

    // ---- Bias + store ----
    float4* orow = out + (size_t)r * (INSIZE / 4);
    #pragma unroll
    for (int k = 0; k < 4; ++k) {
        float4 b = bias[k * 32 + lane];
        float4 o;
        o.x = m[k].x + b.x; o.y = m[k].y + b.y;
        o.z = m[k].z + b.z; o.w = m[k].w + b.w;
        orow[k * 32 + lane] = o;
    }
}

// ---------------------------------------------------------------------------
extern "C" void kernel_launch(void* const* d_in, const int* in_sizes, int n_in,
                              void* d_out, int out_size)
{
    (void)in_sizes; (void)n_in; (void)out_size;
    const float* x    = (const float*)d_in[0];
    const float* p    = (const float*)d_in[1];
    const float* U    = (const float*)d_in[2];
    const float* V    = (const float*)d_in[3];
    const float* bias = (const float*)d_in[4];

    prep_kernel<<<1, 1024>>>(p, U, V);
    spectral_main<<<BATCH / ROWS_PER_BLOCK, 512>>>(
        (const float4*)x, U, V, (const float4*)bias, (float4*)d_out);
}

// round 2
// speedup vs baseline: 1.5106x; 1.5106x over previous
#include <cuda_runtime.h>

#define INSIZE 512
#define NVEC   (INSIZE / 4)   // 128 float4 per row
#define NREFL  64
#define BATCH  8192

__device__ __align__(16) float g_sigma[INSIZE];
__device__ float g_beta_u[NREFL];
__device__ float g_beta_v[NREFL];

// ---------------------------------------------------------------------------
// Prep: sigma from p, beta = 2/(u.u). U/V rows are already upper-triangular
// in memory (setup applies triu), so full-row dots are exact.
// ---------------------------------------------------------------------------
__global__ void prep_kernel(const float* __restrict__ p,
                            const float* __restrict__ U,
                            const float* __restrict__ V)
{
    const int t = threadIdx.x;
    if (t < INSIZE) {
        float s = 1.0f / (1.0f + expf(-p[t]));
        g_sigma[t] = 0.1f + 0.9f * s;
    }
    const int w = t >> 5, lane = t & 31;
    #pragma unroll
    for (int q = 0; q < 4; ++q) {
        const int n = w + 32 * q;                      // 0..127
        const float* mat = (n < NREFL) ? U : V;
        const int row = (n < NREFL) ? n : n - NREFL;
        float ss = 0.f;
        #pragma unroll
        for (int j = lane; j < INSIZE; j += 32) {
            float v = mat[row * INSIZE + j];
            ss += v * v;
        }
        #pragma unroll
        for (int o = 16; o > 0; o >>= 1) ss += __shfl_xor_sync(0xffffffffu, ss, o);
        if (lane == 0) {
            float b = 2.0f / ss;
            if (n < NREFL) g_beta_u[row] = b; else g_beta_v[row] = b;
        }
    }
}

// ---------------------------------------------------------------------------
// Main: each warp owns TWO batch rows, held entirely in registers
// (2 x 4 float4 per lane). Reflectors streamed from global (L2 broadcast)
// with one-deep register prefetch. No shared memory, no barriers.
// ---------------------------------------------------------------------------
__global__ __launch_bounds__(256, 2)
void spectral_main(const float4* __restrict__ x,
                   const float4* __restrict__ U4,
                   const float4* __restrict__ V4,
                   const float4* __restrict__ bias,
                   float4* __restrict__ out)
{
    const int t    = threadIdx.x;
    const int w    = t >> 5;
    const int lane = t & 31;
    const int r    = (blockIdx.x * 8 + w) * 2;   // two consecutive rows

    const float4* xa = x + (size_t)r * NVEC;
    const float4* xb = xa + NVEC;
    float4 a[4], b[4];
    #pragma unroll
    for (int k = 0; k < 4; ++k) { a[k] = xa[k * 32 + lane]; b[k] = xb[k * 32 + lane]; }

    float4 uc[4], un[4];

    // ================= U chain: i = 0 .. 63 =================
    #pragma unroll
    for (int k = 0; k < 4; ++k) uc[k] = __ldg(&U4[k * 32 + lane]);

    #pragma unroll 1
    for (int i = 0; i < NREFL; ++i) {
        const int inext = (i + 1 < NREFL) ? i + 1 : i;      // harmless reload on last
        const float4* nx = U4 + (size_t)inext * NVEC;
        #pragma unroll
        for (int k = 0; k < 4; ++k) un[k] = __ldg(&nx[k * 32 + lane]);

        float da = 0.f, db = 0.f;
        #pragma unroll
        for (int k = 0; k < 4; ++k) {
            da += a[k].x * uc[k].x + a[k].y * uc[k].y + a[k].z * uc[k].z + a[k].w * uc[k].w;
            db += b[k].x * uc[k].x + b[k].y * uc[k].y + b[k].z * uc[k].z + b[k].w * uc[k].w;
        }
        #pragma unroll
        for (int o = 16; o > 0; o >>= 1) {
            da += __shfl_xor_sync(0xffffffffu, da, o);
            db += __shfl_xor_sync(0xffffffffu, db, o);
        }
        const float beta = g_beta_u[i];
        const float sa = beta * da, sb = beta * db;
        #pragma unroll
        for (int k = 0; k < 4; ++k) {
            a[k].x -= sa * uc[k].x; a[k].y -= sa * uc[k].y;
            a[k].z -= sa * uc[k].z; a[k].w -= sa * uc[k].w;
            b[k].x -= sb * uc[k].x; b[k].y -= sb * uc[k].y;
            b[k].z -= sb * uc[k].z; b[k].w -= sb * uc[k].w;
            uc[k] = un[k];
        }
    }

    // ================= Sigma =================
    {
        const float4* sg = (const float4*)g_sigma;
        #pragma unroll
        for (int k = 0; k < 4; ++k) {
            float4 sv = sg[k * 32 + lane];
            a[k].x *= sv.x; a[k].y *= sv.y; a[k].z *= sv.z; a[k].w *= sv.w;
            b[k].x *= sv.x; b[k].y *= sv.y; b[k].z *= sv.z; b[k].w *= sv.w;
        }
    }

    // ================= V chain: i = 63 .. 0 =================
    #pragma unroll
    for (int k = 0; k < 4; ++k)
        uc[k] = __ldg(&V4[(size_t)(NREFL - 1) * NVEC + k * 32 + lane]);

    #pragma unroll 1
    for (int ii = 0; ii < NREFL; ++ii) {
        const int i     = NREFL - 1 - ii;
        const int inext = (i > 0) ? i - 1 : 0;
        const float4* nx = V4 + (size_t)inext * NVEC;
        #pragma unroll
        for (int k = 0; k < 4; ++k) un[k] = __ldg(&nx[k * 32 + lane]);

        float da = 0.f, db = 0.f;
        #pragma unroll
        for (int k = 0; k < 4; ++k) {
            da += a[k].x * uc[k].x + a[k].y * uc[k].y + a[k].z * uc[k].z + a[k].w * uc[k].w;
            db += b[k].x * uc[k].x + b[k].y * uc[k].y + b[k].z * uc[k].z + b[k].w * uc[k].w;
        }
        #pragma unroll
        for (int o = 16; o > 0; o >>= 1) {
            da += __shfl_xor_sync(0xffffffffu, da, o);
            db += __shfl_xor_sync(0xffffffffu, db, o);
        }
        const float beta = g_beta_v[i];
        const float sa = beta * da, sb = beta * db;
        #pragma unroll
        for (int k = 0; k < 4; ++k) {
            a[k].x -= sa * uc[k].x; a[k].y -= sa * uc[k].y;
            a[k].z -= sa * uc[k].z; a[k].w -= sa * uc[k].w;
            b[k].x -= sb * uc[k].x; b[k].y -= sb * uc[k].y;
            b[k].z -= sb * uc[k].z; b[k].w -= sb * uc[k].w;
            uc[k] = un[k];
        }
    }

    // ================= Bias + store =================
    float4* oa = out + (size_t)r * NVEC;
    float4* ob = oa + NVEC;
    #pragma unroll
    for (int k = 0; k < 4; ++k) {
        float4 bi = bias[k * 32 + lane];
        float4 o0, o1;
        o0.x = a[k].x + bi.x; o0.y = a[k].y + bi.y;
        o0.z = a[k].z + bi.z; o0.w = a[k].w + bi.w;
        o1.x = b[k].x + bi.x; o1.y = b[k].y + bi.y;
        o1.z = b[k].z + bi.z; o1.w = b[k].w + bi.w;
        oa[k * 32 + lane] = o0;
        ob[k * 32 + lane] = o1;
    }
}

// ---------------------------------------------------------------------------
extern "C" void kernel_launch(void* const* d_in, const int* in_sizes, int n_in,
                              void* d_out, int out_size)
{
    (void)in_sizes; (void)n_in; (void)out_size;
    const float* x    = (const float*)d_in[0];
    const float* p    = (const float*)d_in[1];
    const float* U    = (const float*)d_in[2];
    const float* V    = (const float*)d_in[3];
    const float* bias = (const float*)d_in[4];

    prep_kernel<<<1, 1024>>>(p, U, V);
    // 8192 rows / (8 warps * 2 rows) = 512 blocks
    spectral_main<<<BATCH / 16, 256>>>(
        (const float4*)x, (const float4*)U, (const float4*)V,
        (const float4*)bias, (float4*)d_out);
}

// round 5
// speedup vs baseline: 1.8455x; 1.2217x over previous
#include <cuda_runtime.h>
#include <cuda_fp16.h>
#include <cstdint>

#define INSIZE 512
#define NVEC   (INSIZE / 4)
#define NREFL  64
#define BATCH  8192

// ---------------- device scratch ----------------
__device__ float g_sigma[INSIZE];
__device__ float g_beta_u[NREFL];
__device__ float g_beta_v[NREFL];
// B operand: [n=512][k=1024] k-contiguous. k<512: M_hi[k][n]; k>=512: M_lo[k-512][n]
__device__ __half g_MT[512 * 1024];
__device__ __half g_xh[BATCH * INSIZE];

// ---------------- helpers ----------------
__device__ __forceinline__ uint32_t smem_u32(const void* p) {
    uint32_t a;
    asm("{ .reg .u64 t; cvta.to.shared.u64 t, %1; cvt.u32.u64 %0, t; }" : "=r"(a) : "l"(p));
    return a;
}
__device__ __forceinline__ void cp_async16(uint32_t dst, const void* src) {
    asm volatile("cp.async.cg.shared.global [%0], [%1], 16;" :: "r"(dst), "l"(src) : "memory");
}
#define CP_COMMIT() asm volatile("cp.async.commit_group;" ::: "memory")
#define CP_WAIT1()  asm volatile("cp.async.wait_group 1;" ::: "memory")
// 64B-row swizzle: XOR 16B-column (bits 4:5) with (row>>1)&3 (bits 7:8)
#define SWZ64(o) ((o) ^ (((o) >> 3) & 0x30))

__device__ __forceinline__ void ldsm_x4(uint32_t* r, uint32_t addr) {
    asm volatile("ldmatrix.sync.aligned.m8n8.x4.shared.b16 {%0,%1,%2,%3}, [%4];"
                 : "=r"(r[0]), "=r"(r[1]), "=r"(r[2]), "=r"(r[3]) : "r"(addr));
}
__device__ __forceinline__ void mma16816(float* d, const uint32_t* a, const uint32_t* b) {
    asm volatile("mma.sync.aligned.m16n8k16.row.col.f32.f16.f16.f32 "
                 "{%0,%1,%2,%3}, {%4,%5,%6,%7}, {%8,%9}, {%0,%1,%2,%3};"
                 : "+f"(d[0]), "+f"(d[1]), "+f"(d[2]), "+f"(d[3])
                 : "r"(a[0]), "r"(a[1]), "r"(a[2]), "r"(a[3]), "r"(b[0]), "r"(b[1]));
}

// ---------------------------------------------------------------------------
// Prep: sigma + betas
// ---------------------------------------------------------------------------
__global__ void prep_kernel(const float* __restrict__ p,
                            const float* __restrict__ U,
                            const float* __restrict__ V)
{
    const int t = threadIdx.x;
    if (t < INSIZE) {
        float s = 1.0f / (1.0f + expf(-p[t]));
        g_sigma[t] = 0.1f + 0.9f * s;
    }
    const int w = t >> 5, lane = t & 31;
    #pragma unroll
    for (int q = 0; q < 4; ++q) {
        const int n = w + 32 * q;
        const float* mat = (n < NREFL) ? U : V;
        const int row = (n < NREFL) ? n : n - NREFL;
        float ss = 0.f;
        #pragma unroll
        for (int j = lane; j < INSIZE; j += 32) {
            float v = mat[row * INSIZE + j];
            ss += v * v;
        }
        #pragma unroll
        for (int o = 16; o > 0; o >>= 1) ss += __shfl_xor_sync(0xffffffffu, ss, o);
        if (lane == 0) {
            float b = 2.0f / ss;
            if (n < NREFL) g_beta_u[row] = b; else g_beta_v[row] = b;
        }
    }
}

// ---------------------------------------------------------------------------
// chain_m: reflection chain + sigma applied to identity rows -> rows of M.
// Writes M^T split fp16 hi/lo into g_MT. 2 rows per warp (R2-validated math).
// ---------------------------------------------------------------------------
__global__ __launch_bounds__(256, 2)
void chain_m(const float4* __restrict__ U4, const float4* __restrict__ V4)
{
    const int t = threadIdx.x;
    const int w = t >> 5;
    const int lane = t & 31;
    const int r = (blockIdx.x * 8 + w) * 2;

    float4 a[4], b[4];
    #pragma unroll
    for (int k = 0; k < 4; ++k) {
        a[k] = make_float4(0.f, 0.f, 0.f, 0.f);
        b[k] = make_float4(0.f, 0.f, 0.f, 0.f);
    }
    {
        int k = r >> 7, rem = r & 127;
        if ((rem >> 2) == lane) ((float*)&a[k])[rem & 3] = 1.0f;
        int r2 = r + 1;
        k = r2 >> 7; rem = r2 & 127;
        if ((rem >> 2) == lane) ((float*)&b[k])[rem & 3] = 1.0f;
    }

    float4 uc[4], un[4];
    #pragma unroll
    for (int k = 0; k < 4; ++k) uc[k] = __ldg(&U4[k * 32 + lane]);
    #pragma unroll 1
    for (int i = 0; i < NREFL; ++i) {
        const int inext = (i + 1 < NREFL) ? i + 1 : i;
        const float4* nx = U4 + (size_t)inext * NVEC;
        #pragma unroll
        for (int k = 0; k < 4; ++k) un[k] = __ldg(&nx[k * 32 + lane]);
        float da = 0.f, db = 0.f;
        #pragma unroll
        for (int k = 0; k < 4; ++k) {
            da += a[k].x*uc[k].x + a[k].y*uc[k].y + a[k].z*uc[k].z + a[k].w*uc[k].w;
            db += b[k].x*uc[k].x + b[k].y*uc[k].y + b[k].z*uc[k].z + b[k].w*uc[k].w;
        }
        #pragma unroll
        for (int o = 16; o > 0; o >>= 1) {
            da += __shfl_xor_sync(0xffffffffu, da, o);
            db += __shfl_xor_sync(0xffffffffu, db, o);
        }
        const float beta = g_beta_u[i];
        const float sa = beta * da, sb = beta * db;
        #pragma unroll
        for (int k = 0; k < 4; ++k) {
            a[k].x -= sa*uc[k].x; a[k].y -= sa*uc[k].y; a[k].z -= sa*uc[k].z; a[k].w -= sa*uc[k].w;
            b[k].x -= sb*uc[k].x; b[k].y -= sb*uc[k].y; b[k].z -= sb*uc[k].z; b[k].w -= sb*uc[k].w;
            uc[k] = un[k];
        }
    }
    {
        const float4* sg = (const float4*)g_sigma;
        #pragma unroll
        for (int k = 0; k < 4; ++k) {
            float4 sv = sg[k * 32 + lane];
            a[k].x *= sv.x; a[k].y *= sv.y; a[k].z *= sv.z; a[k].w *= sv.w;
            b[k].x *= sv.x; b[k].y *= sv.y; b[k].z *= sv.z; b[k].w *= sv.w;
        }
    }
    #pragma unroll
    for (int k = 0; k < 4; ++k)
        uc[k] = __ldg(&V4[(size_t)(NREFL - 1) * NVEC + k * 32 + lane]);
    #pragma unroll 1
    for (int ii = 0; ii < NREFL; ++ii) {
        const int i = NREFL - 1 - ii;
        const int inext = (i > 0) ? i - 1 : 0;
        const float4* nx = V4 + (size_t)inext * NVEC;
        #pragma unroll
        for (int k = 0; k < 4; ++k) un[k] = __ldg(&nx[k * 32 + lane]);
        float da = 0.f, db = 0.f;
        #pragma unroll
        for (int k = 0; k < 4; ++k) {
            da += a[k].x*uc[k].x + a[k].y*uc[k].y + a[k].z*uc[k].z + a[k].w*uc[k].w;
            db += b[k].x*uc[k].x + b[k].y*uc[k].y + b[k].z*uc[k].z + b[k].w*uc[k].w;
        }
        #pragma unroll
        for (int o = 16; o > 0; o >>= 1) {
            da += __shfl_xor_sync(0xffffffffu, da, o);
            db += __shfl_xor_sync(0xffffffffu, db, o);
        }
        const float beta = g_beta_v[i];
        const float sa = beta * da, sb = beta * db;
        #pragma unroll
        for (int k = 0; k < 4; ++k) {
            a[k].x -= sa*uc[k].x; a[k].y -= sa*uc[k].y; a[k].z -= sa*uc[k].z; a[k].w -= sa*uc[k].w;
            b[k].x -= sb*uc[k].x; b[k].y -= sb*uc[k].y; b[k].z -= sb*uc[k].z; b[k].w -= sb*uc[k].w;
            uc[k] = un[k];
        }
    }

    // store M^T split fp16: hi at [n][r], lo at [n][512+r]
    #pragma unroll
    for (int k = 0; k < 4; ++k) {
        const float va[4] = { a[k].x, a[k].y, a[k].z, a[k].w };
        const float vb[4] = { b[k].x, b[k].y, b[k].z, b[k].w };
        #pragma unroll
        for (int c = 0; c < 4; ++c) {
            const int n = k * 128 + lane * 4 + c;
            __half ha = __float2half_rn(va[c]);
            __half la = __float2half_rn(va[c] - __half2float(ha));
            __half hb = __float2half_rn(vb[c]);
            __half lb = __float2half_rn(vb[c] - __half2float(hb));
            size_t base = (size_t)n * 1024;
            g_MT[base + r]           = ha;
            g_MT[base + 512 + r]     = la;
            g_MT[base + r + 1]       = hb;
            g_MT[base + 512 + r + 1] = lb;
        }
    }
}

// ---------------------------------------------------------------------------
// conv_x: x fp32 -> fp16
// ---------------------------------------------------------------------------
__global__ __launch_bounds__(256)
void conv_x(const float4* __restrict__ x)
{
    const int i = blockIdx.x * 256 + threadIdx.x;
    float4 v = x[i];
    __half2* h = (__half2*)g_xh;
    h[i * 2 + 0] = __floats2half2_rn(v.x, v.y);
    h[i * 2 + 1] = __floats2half2_rn(v.z, v.w);
}

// ---------------------------------------------------------------------------
// GEMM: out[8192,512] = A[8192,1024] * B[512,1024]^T + bias
// A = [x_h | x_h] (k mod 512), B = g_MT. CTA 128x128, K-step 32, 3 stages.
// ---------------------------------------------------------------------------
#define TM 128
#define TN 128
#define NKS 32
#define STG 16384       // 8KB A + 8KB B per stage

__global__ __launch_bounds__(256, 2)
void gemm_kernel(float* __restrict__ out, const float* __restrict__ bias)
{
    __shared__ __align__(1024) uint8_t smem[3 * STG];   // 48KB static
    const uint32_t sbase = smem_u32(smem);
    const int t = threadIdx.x;
    const int lane = t & 31, wid = t >> 5;
    const int wm = wid & 3, wn = wid >> 2;         // 4 x 2 warp grid
    const int m0 = blockIdx.x * TM, n0 = blockIdx.y * TN;

    float acc[2][8][4];
    #pragma unroll
    for (int fm = 0; fm < 2; ++fm)
        #pragma unroll
        for (int fn = 0; fn < 8; ++fn)
            #pragma unroll
            for (int j = 0; j < 4; ++j) acc[fm][fn][j] = 0.f;

    auto load_stage = [&](int st, int ks) {
        const __half* Ab = g_xh + (size_t)m0 * 512 + (ks & 15) * 32;
        const __half* Bb = g_MT + (size_t)n0 * 1024 + ks * 32;
        const uint32_t sA = sbase + st * STG;
        const uint32_t sB = sA + 8192;
        #pragma unroll
        for (int i = 0; i < 2; ++i) {
            const int idx = t + i * 256;
            const int row = idx >> 2, c = idx & 3;
            cp_async16(sA + SWZ64((uint32_t)(row * 64 + c * 16)),
                       Ab + (size_t)row * 512 + c * 8);
        }
        #pragma unroll
        for (int i = 0; i < 2; ++i) {
            const int idx = t + i * 256;
            const int row = idx >> 2, c = idx & 3;
            cp_async16(sB + SWZ64((uint32_t)(row * 64 + c * 16)),
                       Bb + (size_t)row * 1024 + c * 8);
        }
    };

    auto compute_stage = [&](int st) {
        const uint32_t sA = sbase + st * STG;
        const uint32_t sB = sA + 8192;
        #pragma unroll
        for (int kf = 0; kf < 2; ++kf) {
            uint32_t a[2][4], b[4][4];
            #pragma unroll
            for (int fm = 0; fm < 2; ++fm) {
                const int row = wm * 32 + fm * 16 + (lane & 15);
                const int c   = kf * 2 + (lane >> 4);
                ldsm_x4(a[fm], sA + SWZ64((uint32_t)(row * 64 + c * 16)));
            }
            #pragma unroll
            for (int fp = 0; fp < 4; ++fp) {
                const int row = wn * 64 + fp * 16 + ((lane >> 4) << 3) + (lane & 7);
                const int c   = kf * 2 + ((lane >> 3) & 1);
                ldsm_x4(b[fp], sB + SWZ64((uint32_t)(row * 64 + c * 16)));
            }
            #pragma unroll
            for (int fm = 0; fm < 2; ++fm)
                #pragma unroll
                for (int fn = 0; fn < 8; ++fn)
                    mma16816(acc[fm][fn], a[fm], &b[fn >> 1][(fn & 1) * 2]);
        }
    };

    // prologue
    load_stage(0, 0); CP_COMMIT();
    load_stage(1, 1); CP_COMMIT();

    #pragma unroll 1
    for (int ks = 0; ks < NKS; ++ks) {
        CP_WAIT1();
        __syncthreads();
        const int kn = ks + 2;
        if (kn < NKS) load_stage(kn % 3, kn);
        CP_COMMIT();                 // unconditional: keeps group accounting exact
        compute_stage(ks % 3);
    }

    // epilogue: bias + store
    #pragma unroll
    for (int fm = 0; fm < 2; ++fm) {
        const int r = m0 + wm * 32 + fm * 16 + (lane >> 2);
        #pragma unroll
        for (int fn = 0; fn < 8; ++fn) {
            const int cb = n0 + wn * 64 + fn * 8 + (lane & 3) * 2;
            const float2 bi = __ldg((const float2*)(bias + cb));
            float2 v0, v1;
            v0.x = acc[fm][fn][0] + bi.x; v0.y = acc[fm][fn][1] + bi.y;
            v1.x = acc[fm][fn][2] + bi.x; v1.y = acc[fm][fn][3] + bi.y;
            *(float2*)(out + (size_t)r * 512 + cb)       = v0;
            *(float2*)(out + (size_t)(r + 8) * 512 + cb) = v1;
        }
    }
}

// ---------------------------------------------------------------------------
extern "C" void kernel_launch(void* const* d_in, const int* in_sizes, int n_in,
                              void* d_out, int out_size)
{
    (void)in_sizes; (void)n_in; (void)out_size;
    const float* x    = (const float*)d_in[0];
    const float* p    = (const float*)d_in[1];
    const float* U    = (const float*)d_in[2];
    const float* V    = (const float*)d_in[3];
    const float* bias = (const float*)d_in[4];

    prep_kernel<<<1, 1024>>>(p, U, V);
    conv_x<<<BATCH * INSIZE / 4 / 256, 256>>>((const float4*)x);
    chain_m<<<32, 256>>>((const float4*)U, (const float4*)V);
    gemm_kernel<<<dim3(BATCH / TM, 512 / TN), 256>>>((float*)d_out, bias);
}

// round 9
// speedup vs baseline: 2.1544x; 1.1674x over previous
#include <cuda_runtime.h>
#include <cuda_fp16.h>
#include <cstdint>

#define INSIZE 512
#define NVEC   (INSIZE / 4)
#define NREFL  64
#define BATCH  8192

// ---------------- device scratch ----------------
__device__ float g_sigma[INSIZE];
__device__ float g_beta_u[NREFL];
__device__ float g_beta_v[NREFL];
__device__ float g_pair[2][16][6];     // within-quad pair dots, [mat][quad][pair]
__device__ float g_T4[2][16][16];      // per-group 4x4 T (row-major), [mat][group]
__device__ __half g_MT[512 * 512];     // M^T fp16: [n][k] k-contiguous
__device__ __half g_xh[BATCH * INSIZE];

// ---------------- helpers ----------------
__device__ __forceinline__ uint32_t smem_u32(const void* p) {
    uint32_t a;
    asm("{ .reg .u64 t; cvta.to.shared.u64 t, %1; cvt.u32.u64 %0, t; }" : "=r"(a) : "l"(p));
    return a;
}
__device__ __forceinline__ void cp_async16(uint32_t dst, const void* src) {
    asm volatile("cp.async.cg.shared.global [%0], [%1], 16;" :: "r"(dst), "l"(src) : "memory");
}
#define CP_COMMIT() asm volatile("cp.async.commit_group;" ::: "memory")
#define CP_WAIT1()  asm volatile("cp.async.wait_group 1;" ::: "memory")
#define SWZ64(o) ((o) ^ (((o) >> 3) & 0x30))

__device__ __forceinline__ void ldsm_x4(uint32_t* r, uint32_t addr) {
    asm volatile("ldmatrix.sync.aligned.m8n8.x4.shared.b16 {%0,%1,%2,%3}, [%4];"
                 : "=r"(r[0]), "=r"(r[1]), "=r"(r[2]), "=r"(r[3]) : "r"(addr));
}
__device__ __forceinline__ void mma16816(float* d, const uint32_t* a, const uint32_t* b) {
    asm volatile("mma.sync.aligned.m16n8k16.row.col.f32.f16.f16.f32 "
                 "{%0,%1,%2,%3}, {%4,%5,%6,%7}, {%8,%9}, {%0,%1,%2,%3};"
                 : "+f"(d[0]), "+f"(d[1]), "+f"(d[2]), "+f"(d[3])
                 : "r"(a[0]), "r"(a[1]), "r"(a[2]), "r"(a[3]), "r"(b[0]), "r"(b[1]));
}

// ---------------------------------------------------------------------------
// prep: sigma, betas, within-quad pair dots, and the 32 group T4 matrices.
// Single block of 1024 so phases can be ordered with __syncthreads.
// ---------------------------------------------------------------------------
__global__ void prep_kernel(const float* __restrict__ p,
                            const float* __restrict__ U,
                            const float* __restrict__ V)
{
    const int t = threadIdx.x;
    const int w = t >> 5, lane = t & 31;

    if (t < INSIZE) {
        float s = 1.0f / (1.0f + expf(-p[t]));
        g_sigma[t] = 0.1f + 0.9f * s;
    }
    // betas: 128 norms
    #pragma unroll
    for (int q = 0; q < 4; ++q) {
        const int n = w + 32 * q;
        const float* mat = (n < NREFL) ? U : V;
        const int row = (n < NREFL) ? n : n - NREFL;
        float ss = 0.f;
        for (int j = lane; j < INSIZE; j += 32) {
            float v = mat[row * INSIZE + j];
            ss += v * v;
        }
        #pragma unroll
        for (int o = 16; o > 0; o >>= 1) ss += __shfl_xor_sync(0xffffffffu, ss, o);
        if (lane == 0) {
            float b = 2.0f / ss;
            if (n < NREFL) g_beta_u[row] = b; else g_beta_v[row] = b;
        }
    }
    // pair dots: 2 mats x 16 quads x 6 pairs = 192 warp tasks
    const int PJ[6] = {0,0,0,1,1,2};
    const int PK[6] = {1,2,3,2,3,3};
    #pragma unroll
    for (int rnd = 0; rnd < 6; ++rnd) {
        const int task = w + 32 * rnd;                 // 0..191
        const int m = task / 96;
        const int rest = task - m * 96;
        const int quad = rest / 6, pr = rest - quad * 6;
        const float* mat = m ? V : U;
        const float* ra = mat + (quad * 4 + PJ[pr]) * INSIZE;
        const float* rb = mat + (quad * 4 + PK[pr]) * INSIZE;
        float ss = 0.f;
        for (int j = lane; j < INSIZE; j += 32) ss += ra[j] * rb[j];
        #pragma unroll
        for (int o = 16; o > 0; o >>= 1) ss += __shfl_xor_sync(0xffffffffu, ss, o);
        if (lane == 0) g_pair[m][quad][pr] = ss;
    }
    __syncthreads();

    // T4 build: 32 threads, one group each
    if (t < 32) {
        const int m = t >> 4, g = t & 15;
        int pix[4][4];
        pix[0][1] = 0; pix[0][2] = 1; pix[0][3] = 2;
        pix[1][2] = 3; pix[1][3] = 4; pix[2][3] = 5;
        float L[4][4];
        if (m == 0) {           // U group g: idx_a = 4g + a (ascending application)
            for (int a = 0; a < 4; ++a) L[a][a] = 1.0f / g_beta_u[4 * g + a];
            for (int a = 0; a < 4; ++a)
                for (int c = a + 1; c < 4; ++c)
                    L[a][c] = g_pair[0][g][pix[a][c]];
        } else {                // V group g: idx_a = 63 - 4g - a (descending)
            const int quad = 15 - g;
            for (int a = 0; a < 4; ++a) L[a][a] = 1.0f / g_beta_v[63 - 4 * g - a];
            for (int a = 0; a < 4; ++a)
                for (int c = a + 1; c < 4; ++c)
                    L[a][c] = g_pair[1][quad][pix[3 - c][3 - a]];
        }
        float T[4][4];
        for (int a = 0; a < 4; ++a)
            for (int c = 0; c < 4; ++c) T[a][c] = 0.f;
        for (int c = 0; c < 4; ++c) {
            T[c][c] = 1.0f / L[c][c];
            for (int a = c - 1; a >= 0; --a) {
                float s = 0.f;
                for (int mm = a + 1; mm <= c; ++mm) s += L[a][mm] * T[mm][c];
                T[a][c] = -s / L[a][a];
            }
        }
        for (int a = 0; a < 4; ++a)
            for (int c = 0; c < 4; ++c) g_T4[m][g][a * 4 + c] = T[a][c];
    }
}

// ---------------------------------------------------------------------------
// chain_m_wy: blocked (rank-4) Householder chain applied to identity rows.
// 32 serial block-steps instead of 128 reflections. 2 rows per warp.
// Writes M^T fp16 (hi only) into g_MT.
// ---------------------------------------------------------------------------
__global__ __launch_bounds__(256)
void chain_m_wy(const float4* __restrict__ U4, const float4* __restrict__ V4)
{
    const int t = threadIdx.x;
    const int w = t >> 5;
    const int lane = t & 31;
    const int r = (blockIdx.x * 8 + w) * 2;

    float4 a[4], b[4];
    #pragma unroll
    for (int k = 0; k < 4; ++k) {
        a[k] = make_float4(0.f, 0.f, 0.f, 0.f);
        b[k] = make_float4(0.f, 0.f, 0.f, 0.f);
    }
    {
        int k = r >> 7, rem = r & 127;
        if ((rem >> 2) == lane) ((float*)&a[k])[rem & 3] = 1.0f;
        int r2 = r + 1;
        k = r2 >> 7; rem = r2 & 127;
        if ((rem >> 2) == lane) ((float*)&b[k])[rem & 3] = 1.0f;
    }

    // ---- U phase: 16 groups, ascending ----
    #pragma unroll 1
    for (int g = 0; g < 16; ++g) {
        float4 u[4][4];
        #pragma unroll
        for (int j = 0; j < 4; ++j) {
            const float4* up = U4 + (size_t)(4 * g + j) * NVEC;
            #pragma unroll
            for (int k = 0; k < 4; ++k) u[j][k] = __ldg(&up[k * 32 + lane]);
        }
        float ca[4], cb[4];
        #pragma unroll
        for (int j = 0; j < 4; ++j) {
            float sa = 0.f, sb = 0.f;
            #pragma unroll
            for (int k = 0; k < 4; ++k) {
                sa += a[k].x*u[j][k].x + a[k].y*u[j][k].y + a[k].z*u[j][k].z + a[k].w*u[j][k].w;
                sb += b[k].x*u[j][k].x + b[k].y*u[j][k].y + b[k].z*u[j][k].z + b[k].w*u[j][k].w;
            }
            ca[j] = sa; cb[j] = sb;
        }
        #pragma unroll
        for (int o = 16; o > 0; o >>= 1) {
            #pragma unroll
            for (int j = 0; j < 4; ++j) {
                ca[j] += __shfl_xor_sync(0xffffffffu, ca[j], o);
                cb[j] += __shfl_xor_sync(0xffffffffu, cb[j], o);
            }
        }
        const float* Tm = g_T4[0][g];
        float da[4], db[4];
        #pragma unroll
        for (int c = 0; c < 4; ++c) {
            float sa = 0.f, sb = 0.f;
            #pragma unroll
            for (int j = 0; j < 4; ++j) {
                const float tv = __ldg(&Tm[j * 4 + c]);
                sa += ca[j] * tv; sb += cb[j] * tv;
            }
            da[c] = sa; db[c] = sb;
        }
        #pragma unroll
        for (int k = 0; k < 4; ++k)
            #pragma unroll
            for (int c = 0; c < 4; ++c) {
                a[k].x -= da[c]*u[c][k].x; a[k].y -= da[c]*u[c][k].y;
                a[k].z -= da[c]*u[c][k].z; a[k].w -= da[c]*u[c][k].w;
                b[k].x -= db[c]*u[c][k].x; b[k].y -= db[c]*u[c][k].y;
                b[k].z -= db[c]*u[c][k].z; b[k].w -= db[c]*u[c][k].w;
            }
    }

    // ---- Sigma ----
    {
        const float4* sg = (const float4*)g_sigma;
        #pragma unroll
        for (int k = 0; k < 4; ++k) {
            float4 sv = sg[k * 32 + lane];
            a[k].x *= sv.x; a[k].y *= sv.y; a[k].z *= sv.z; a[k].w *= sv.w;
            b[k].x *= sv.x; b[k].y *= sv.y; b[k].z *= sv.z; b[k].w *= sv.w;
        }
    }

    // ---- V phase: 16 groups, reflector indices descending ----
    #pragma unroll 1
    for (int g = 0; g < 16; ++g) {
        float4 u[4][4];
        #pragma unroll
        for (int j = 0; j < 4; ++j) {
            const float4* vp = V4 + (size_t)(63 - 4 * g - j) * NVEC;
            #pragma unroll
            for (int k = 0; k < 4; ++k) u[j][k] = __ldg(&vp[k * 32 + lane]);
        }
        float ca[4], cb[4];
        #pragma unroll
        for (int j = 0; j < 4; ++j) {
            float sa = 0.f, sb = 0.f;
            #pragma unroll
            for (int k = 0; k < 4; ++k) {
                sa += a[k].x*u[j][k].x + a[k].y*u[j][k].y + a[k].z*u[j][k].z + a[k].w*u[j][k].w;
                sb += b[k].x*u[j][k].x + b[k].y*u[j][k].y + b[k].z*u[j][k].z + b[k].w*u[j][k].w;
            }
            ca[j] = sa; cb[j] = sb;
        }
        #pragma unroll
        for (int o = 16; o > 0; o >>= 1) {
            #pragma unroll
            for (int j = 0; j < 4; ++j) {
                ca[j] += __shfl_xor_sync(0xffffffffu, ca[j], o);
                cb[j] += __shfl_xor_sync(0xffffffffu, cb[j], o);
            }
        }
        const float* Tm = g_T4[1][g];
        float da[4], db[4];
        #pragma unroll
        for (int c = 0; c < 4; ++c) {
            float sa = 0.f, sb = 0.f;
            #pragma unroll
            for (int j = 0; j < 4; ++j) {
                const float tv = __ldg(&Tm[j * 4 + c]);
                sa += ca[j] * tv; sb += cb[j] * tv;
            }
            da[c] = sa; db[c] = sb;
        }
        #pragma unroll
        for (int k = 0; k < 4; ++k)
            #pragma unroll
            for (int c = 0; c < 4; ++c) {
                a[k].x -= da[c]*u[c][k].x; a[k].y -= da[c]*u[c][k].y;
                a[k].z -= da[c]*u[c][k].z; a[k].w -= da[c]*u[c][k].w;
                b[k].x -= db[c]*u[c][k].x; b[k].y -= db[c]*u[c][k].y;
                b[k].z -= db[c]*u[c][k].z; b[k].w -= db[c]*u[c][k].w;
            }
    }

    // ---- store M^T fp16 ----
    #pragma unroll
    for (int k = 0; k < 4; ++k) {
        const float va[4] = { a[k].x, a[k].y, a[k].z, a[k].w };
        const float vb[4] = { b[k].x, b[k].y, b[k].z, b[k].w };
        #pragma unroll
        for (int c = 0; c < 4; ++c) {
            const int n = k * 128 + lane * 4 + c;
            g_MT[(size_t)n * 512 + r]     = __float2half_rn(va[c]);
            g_MT[(size_t)n * 512 + r + 1] = __float2half_rn(vb[c]);
        }
    }
}

// ---------------------------------------------------------------------------
// conv_x: x fp32 -> fp16
// ---------------------------------------------------------------------------
__global__ __launch_bounds__(256)
void conv_x(const float4* __restrict__ x)
{
    const int i = blockIdx.x * 256 + threadIdx.x;
    float4 v = x[i];
    __half2* h = (__half2*)g_xh;
    h[i * 2 + 0] = __floats2half2_rn(v.x, v.y);
    h[i * 2 + 1] = __floats2half2_rn(v.z, v.w);
}

// ---------------------------------------------------------------------------
// GEMM: out[8192,512] = x_h[8192,512] * M^T[512,512]^T + bias. K=512.
// CTA 128x128, K-step 32, 3-stage cp.async pipeline.
// ---------------------------------------------------------------------------
#define TM 128
#define TN 128
#define NKS 16
#define STG 16384       // 8KB A + 8KB B per stage

__global__ __launch_bounds__(256, 2)
void gemm_kernel(float* __restrict__ out, const float* __restrict__ bias)
{
    __shared__ __align__(1024) uint8_t smem[3 * STG];
    const uint32_t sbase = smem_u32(smem);
    const int t = threadIdx.x;
    const int lane = t & 31, wid = t >> 5;
    const int wm = wid & 3, wn = wid >> 2;
    const int m0 = blockIdx.x * TM, n0 = blockIdx.y * TN;

    float acc[2][8][4];
    #pragma unroll
    for (int fm = 0; fm < 2; ++fm)
        #pragma unroll
        for (int fn = 0; fn < 8; ++fn)
            #pragma unroll
            for (int j = 0; j < 4; ++j) acc[fm][fn][j] = 0.f;

    auto load_stage = [&](int st, int ks) {
        const __half* Ab = g_xh + (size_t)m0 * 512 + ks * 32;
        const __half* Bb = g_MT + (size_t)n0 * 512 + ks * 32;
        const uint32_t sA = sbase + st * STG;
        const uint32_t sB = sA + 8192;
        #pragma unroll
        for (int i = 0; i < 2; ++i) {
            const int idx = t + i * 256;
            const int row = idx >> 2, c = idx & 3;
            cp_async16(sA + SWZ64((uint32_t)(row * 64 + c * 16)),
                       Ab + (size_t)row * 512 + c * 8);
        }
        #pragma unroll
        for (int i = 0; i < 2; ++i) {
            const int idx = t + i * 256;
            const int row = idx >> 2, c = idx & 3;
            cp_async16(sB + SWZ64((uint32_t)(row * 64 + c * 16)),
                       Bb + (size_t)row * 512 + c * 8);
        }
    };

    auto compute_stage = [&](int st) {
        const uint32_t sA = sbase + st * STG;
        const uint32_t sB = sA + 8192;
        #pragma unroll
        for (int kf = 0; kf < 2; ++kf) {
            uint32_t a[2][4], b[4][4];
            #pragma unroll
            for (int fm = 0; fm < 2; ++fm) {
                const int row = wm * 32 + fm * 16 + (lane & 15);
                const int c   = kf * 2 + (lane >> 4);
                ldsm_x4(a[fm], sA + SWZ64((uint32_t)(row * 64 + c * 16)));
            }
            #pragma unroll
            for (int fp = 0; fp < 4; ++fp) {
                const int row = wn * 64 + fp * 16 + ((lane >> 4) << 3) + (lane & 7);
                const int c   = kf * 2 + ((lane >> 3) & 1);
                ldsm_x4(b[fp], sB + SWZ64((uint32_t)(row * 64 + c * 16)));
            }
            #pragma unroll
            for (int fm = 0; fm < 2; ++fm)
                #pragma unroll
                for (int fn = 0; fn < 8; ++fn)
                    mma16816(acc[fm][fn], a[fm], &b[fn >> 1][(fn & 1) * 2]);
        }
    };

    load_stage(0, 0); CP_COMMIT();
    load_stage(1, 1); CP_COMMIT();

    #pragma unroll 1
    for (int ks = 0; ks < NKS; ++ks) {
        CP_WAIT1();
        __syncthreads();
        const int kn = ks + 2;
        if (kn < NKS) load_stage(kn % 3, kn);
        CP_COMMIT();
        compute_stage(ks % 3);
    }

    #pragma unroll
    for (int fm = 0; fm < 2; ++fm) {
        const int r = m0 + wm * 32 + fm * 16 + (lane >> 2);
        #pragma unroll
        for (int fn = 0; fn < 8; ++fn) {
            const int cb = n0 + wn * 64 + fn * 8 + (lane & 3) * 2;
            const float2 bi = __ldg((const float2*)(bias + cb));
            float2 v0, v1;
            v0.x = acc[fm][fn][0] + bi.x; v0.y = acc[fm][fn][1] + bi.y;
            v1.x = acc[fm][fn][2] + bi.x; v1.y = acc[fm][fn][3] + bi.y;
            *(float2*)(out + (size_t)r * 512 + cb)       = v0;
            *(float2*)(out + (size_t)(r + 8) * 512 + cb) = v1;
        }
    }
}

// ---------------------------------------------------------------------------
extern "C" void kernel_launch(void* const* d_in, const int* in_sizes, int n_in,
                              void* d_out, int out_size)
{
    (void)in_sizes; (void)n_in; (void)out_size;
    const float* x    = (const float*)d_in[0];
    const float* p    = (const float*)d_in[1];
    const float* U    = (const float*)d_in[2];
    const float* V    = (const float*)d_in[3];
    const float* bias = (const float*)d_in[4];

    prep_kernel<<<1, 1024>>>(p, U, V);
    conv_x<<<BATCH * INSIZE / 4 / 256, 256>>>((const float4*)x);
    chain_m_wy<<<32, 256>>>((const float4*)U, (const float4*)V);
    gemm_kernel<<<dim3(BATCH / TM, 512 / TN), 256>>>((float*)d_out, bias);
}